// round 2
// baseline (speedup 1.0000x reference)
#include <cuda_runtime.h>
#include <cuda_bf16.h>

// Problem constants (fixed by the reference)
#define N_LIG   100000
#define N_TGT   20000
#define N_EDGE  250000
#define LIG_IN  4
#define TGT_IN  1280
#define HID     128
#define ZCOLS   256   // [y_t (W_tl_l) | z_r (W_lt_r)]

// ---------------- scratch (device globals; no allocation allowed) ----------
__device__ float g_accL[(size_t)N_LIG * HID];   // 51.2 MB scatter accumulator
__device__ float g_cntL[N_LIG];
__device__ float g_accT[N_TGT * LIG_IN];
__device__ float g_cntT[N_TGT];
__device__ float g_z[(size_t)N_TGT * ZCOLS];    // fused target projection
__device__ float g_wcat[TGT_IN * ZCOLS];        // packed [W_tl_l | W_lt_r]
__device__ float g_sl[N_LIG];
__device__ float g_st[N_TGT];

// ---------------- pack W_tl_l / W_lt_r into one [1280,256] matrix ----------
__global__ void pack_w_kernel(const float* __restrict__ W_tl_l,
                              const float* __restrict__ W_lt_r) {
    int idx = blockIdx.x * blockDim.x + threadIdx.x;
    if (idx >= TGT_IN * ZCOLS) return;
    int k = idx / ZCOLS;
    int c = idx % ZCOLS;
    g_wcat[idx] = (c < HID) ? W_tl_l[k * HID + c] : W_lt_r[k * HID + (c - HID)];
}

// ---------------- SGEMM: z[M,256] = x_target[M,1280] @ wcat ----------------
#define BM 128
#define BN 128
#define BK 8
#define TM 8
#define TN 8
__global__ __launch_bounds__(256) void sgemm_kernel(
    const float* __restrict__ A,   // [M, K] row-major
    const float* __restrict__ B,   // [K, N] row-major
    float* __restrict__ C,         // [M, N]
    int M, int N, int K) {
    __shared__ float As[BK][BM];
    __shared__ float Bs[BK][BN];

    const int bx = blockIdx.x;           // N tile
    const int by = blockIdx.y;           // M tile
    const int tid = threadIdx.x;

    const int threadCol = tid % (BN / TN);   // 0..15
    const int threadRow = tid / (BN / TN);   // 0..15

    const int rowA = tid >> 1;               // 0..127
    const int colA = (tid & 1) * 4;          // 0 or 4
    const int rowB = tid >> 5;               // 0..7
    const int colB = (tid & 31) * 4;         // 0..124

    const int aRowBase = by * BM;
    float acc[TM][TN];
    #pragma unroll
    for (int i = 0; i < TM; i++)
        #pragma unroll
        for (int j = 0; j < TN; j++) acc[i][j] = 0.f;

    for (int k0 = 0; k0 < K; k0 += BK) {
        // load A tile (transposed into As[k][m])
        float4 av = make_float4(0.f, 0.f, 0.f, 0.f);
        int gr = aRowBase + rowA;
        if (gr < M) av = *(const float4*)(A + (size_t)gr * K + k0 + colA);
        As[colA + 0][rowA] = av.x;
        As[colA + 1][rowA] = av.y;
        As[colA + 2][rowA] = av.z;
        As[colA + 3][rowA] = av.w;
        // load B tile
        float4 bv = *(const float4*)(B + (size_t)(k0 + rowB) * N + bx * BN + colB);
        *(float4*)(&Bs[rowB][colB]) = bv;
        __syncthreads();

        #pragma unroll
        for (int k = 0; k < BK; k++) {
            float ra[TM], rb[TN];
            float4 a0 = *(float4*)(&As[k][threadRow * TM]);
            float4 a1 = *(float4*)(&As[k][threadRow * TM + 4]);
            ra[0]=a0.x; ra[1]=a0.y; ra[2]=a0.z; ra[3]=a0.w;
            ra[4]=a1.x; ra[5]=a1.y; ra[6]=a1.z; ra[7]=a1.w;
            float4 b0 = *(float4*)(&Bs[k][threadCol * TN]);
            float4 b1 = *(float4*)(&Bs[k][threadCol * TN + 4]);
            rb[0]=b0.x; rb[1]=b0.y; rb[2]=b0.z; rb[3]=b0.w;
            rb[4]=b1.x; rb[5]=b1.y; rb[6]=b1.z; rb[7]=b1.w;
            #pragma unroll
            for (int i = 0; i < TM; i++)
                #pragma unroll
                for (int j = 0; j < TN; j++)
                    acc[i][j] = fmaf(ra[i], rb[j], acc[i][j]);
        }
        __syncthreads();
    }

    #pragma unroll
    for (int i = 0; i < TM; i++) {
        int row = aRowBase + threadRow * TM + i;
        if (row < M) {
            float4* cp = (float4*)(C + (size_t)row * N + bx * BN + threadCol * TN);
            cp[0] = make_float4(acc[i][0], acc[i][1], acc[i][2], acc[i][3]);
            cp[1] = make_float4(acc[i][4], acc[i][5], acc[i][6], acc[i][7]);
        }
    }
}

// ---------------- edge scatter: one warp per edge ---------------------------
// accL[src] += y_t[dst] (128 dims), cntL[src]++, accT[dst] += x_lig[src] (4), cntT[dst]++
__global__ __launch_bounds__(256) void edge_scatter_kernel(
    const int* __restrict__ esrc, const int* __restrict__ edst,
    const float* __restrict__ xlig) {
    int warpId = (blockIdx.x * blockDim.x + threadIdx.x) >> 5;
    int lane = threadIdx.x & 31;
    if (warpId >= N_EDGE) return;
    int s = esrc[warpId];
    int d = edst[warpId];
    // gather 128-dim y_t row for this edge's target (cols 0..127 of z)
    float4 y = *(const float4*)(g_z + (size_t)d * ZCOLS + lane * 4);
    float4* a = (float4*)(g_accL + (size_t)s * HID + lane * 4);
#if __CUDA_ARCH__ >= 900
    atomicAdd(a, y);
#else
    float* af = (float*)a;
    atomicAdd(af + 0, y.x); atomicAdd(af + 1, y.y);
    atomicAdd(af + 2, y.z); atomicAdd(af + 3, y.w);
#endif
    if (lane == 0) {
        atomicAdd(&g_cntL[s], 1.f);
        atomicAdd(&g_cntT[d], 1.f);
        float4 xf = *(const float4*)(xlig + (size_t)s * LIG_IN);
        float* t = g_accT + (size_t)d * LIG_IN;
        atomicAdd(t + 0, xf.x); atomicAdd(t + 1, xf.y);
        atomicAdd(t + 2, xf.z); atomicAdd(t + 3, xf.w);
    }
}

// ---------------- target finalize: s_t[t] = <relu(t_out), W_ep[128:256]> ---
__global__ __launch_bounds__(256) void target_final_kernel(
    const float* __restrict__ W_lt_l, const float* __restrict__ b_lt_l,
    const float* __restrict__ W_ep) {
    int t = blockIdx.x * (blockDim.x >> 5) + (threadIdx.x >> 5);
    int lane = threadIdx.x & 31;
    if (t >= N_TGT) return;
    float inv = 1.f / fmaxf(g_cntT[t], 1.f);
    float m0 = g_accT[t * 4 + 0] * inv;
    float m1 = g_accT[t * 4 + 1] * inv;
    float m2 = g_accT[t * 4 + 2] * inv;
    float m3 = g_accT[t * 4 + 3] * inv;
    float sum = 0.f;
    #pragma unroll
    for (int i = 0; i < 4; i++) {
        int h = lane + 32 * i;
        float v = b_lt_l[h] + g_z[(size_t)t * ZCOLS + HID + h];
        v = fmaf(m0, W_lt_l[0 * HID + h], v);
        v = fmaf(m1, W_lt_l[1 * HID + h], v);
        v = fmaf(m2, W_lt_l[2 * HID + h], v);
        v = fmaf(m3, W_lt_l[3 * HID + h], v);
        v = fmaxf(v, 0.f);
        sum = fmaf(v, W_ep[HID + h], sum);
    }
    #pragma unroll
    for (int o = 16; o > 0; o >>= 1) sum += __shfl_xor_sync(0xffffffffu, sum, o);
    if (lane == 0) g_st[t] = sum;
}

// ---------------- ligand finalize: s_l[l] = <relu(l_out), W_ep[0:128]> -----
__global__ __launch_bounds__(256) void ligand_final_kernel(
    const float* __restrict__ xlig, const float* __restrict__ W_tl_r,
    const float* __restrict__ b_tl_l, const float* __restrict__ W_ep) {
    int l = blockIdx.x * (blockDim.x >> 5) + (threadIdx.x >> 5);
    int lane = threadIdx.x & 31;
    if (l >= N_LIG) return;
    float inv = 1.f / fmaxf(g_cntL[l], 1.f);
    float4 xf = *(const float4*)(xlig + (size_t)l * LIG_IN);
    float sum = 0.f;
    #pragma unroll
    for (int i = 0; i < 4; i++) {
        int h = lane + 32 * i;
        float v = b_tl_l[h] + g_accL[(size_t)l * HID + h] * inv;
        v = fmaf(xf.x, W_tl_r[0 * HID + h], v);
        v = fmaf(xf.y, W_tl_r[1 * HID + h], v);
        v = fmaf(xf.z, W_tl_r[2 * HID + h], v);
        v = fmaf(xf.w, W_tl_r[3 * HID + h], v);
        v = fmaxf(v, 0.f);
        sum = fmaf(v, W_ep[h], sum);
    }
    #pragma unroll
    for (int o = 16; o > 0; o >>= 1) sum += __shfl_xor_sync(0xffffffffu, sum, o);
    if (lane == 0) g_sl[l] = sum;
}

// ---------------- edge output ------------------------------------------------
__global__ __launch_bounds__(256) void edge_out_kernel(
    const int* __restrict__ esrc, const int* __restrict__ edst,
    const float* __restrict__ b_ep, float* __restrict__ out) {
    int e = blockIdx.x * blockDim.x + threadIdx.x;
    if (e >= N_EDGE) return;
    out[e] = g_sl[esrc[e]] + g_st[edst[e]] + b_ep[0];
}

// ---------------- launch ----------------------------------------------------
extern "C" void kernel_launch(void* const* d_in, const int* in_sizes, int n_in,
                              void* d_out, int out_size) {
    const float* x_ligand = (const float*)d_in[0];
    const float* x_target = (const float*)d_in[1];
    const int*   edge_src = (const int*)d_in[2];
    const int*   edge_dst = (const int*)d_in[3];
    const float* W_lt_l   = (const float*)d_in[4];
    const float* b_lt_l   = (const float*)d_in[5];
    const float* W_lt_r   = (const float*)d_in[6];
    const float* W_tl_l   = (const float*)d_in[7];
    const float* b_tl_l   = (const float*)d_in[8];
    const float* W_tl_r   = (const float*)d_in[9];
    const float* W_ep     = (const float*)d_in[10];
    const float* b_ep     = (const float*)d_in[11];
    float* out = (float*)d_out;

    // zero the scatter accumulators (graph-capturable async memsets)
    void *pAccL, *pCntL, *pAccT, *pCntT;
    cudaGetSymbolAddress(&pAccL, g_accL);
    cudaGetSymbolAddress(&pCntL, g_cntL);
    cudaGetSymbolAddress(&pAccT, g_accT);
    cudaGetSymbolAddress(&pCntT, g_cntT);
    cudaMemsetAsync(pAccL, 0, (size_t)N_LIG * HID * sizeof(float), 0);
    cudaMemsetAsync(pCntL, 0, (size_t)N_LIG * sizeof(float), 0);
    cudaMemsetAsync(pAccT, 0, (size_t)N_TGT * LIG_IN * sizeof(float), 0);
    cudaMemsetAsync(pCntT, 0, (size_t)N_TGT * sizeof(float), 0);

    // pack weights
    pack_w_kernel<<<(TGT_IN * ZCOLS + 255) / 256, 256>>>(W_tl_l, W_lt_r);

    // fused target projection: z = x_target @ [W_tl_l | W_lt_r]
    {
        float* z; cudaGetSymbolAddress((void**)&z, g_z);
        float* wcat; cudaGetSymbolAddress((void**)&wcat, g_wcat);
        dim3 grid(ZCOLS / BN, (N_TGT + BM - 1) / BM);
        sgemm_kernel<<<grid, 256>>>(x_target, wcat, z, N_TGT, ZCOLS, TGT_IN);
    }

    // edge scatter (one warp per edge)
    {
        int warpsPerBlock = 256 / 32;
        int blocks = (N_EDGE + warpsPerBlock - 1) / warpsPerBlock;
        edge_scatter_kernel<<<blocks, 256>>>(edge_src, edge_dst, x_ligand);
    }

    // per-node scalar reductions
    target_final_kernel<<<(N_TGT + 7) / 8, 256>>>(W_lt_l, b_lt_l, W_ep);
    ligand_final_kernel<<<(N_LIG + 7) / 8, 256>>>(x_ligand, W_tl_r, b_tl_l, W_ep);

    // edge predictions
    edge_out_kernel<<<(N_EDGE + 255) / 256, 256>>>(edge_src, edge_dst, b_ep, out);
}

// round 4
// speedup vs baseline: 2.3562x; 2.3562x over previous
#include <cuda_runtime.h>
#include <cuda_bf16.h>
#include <cstdint>

// Problem constants (fixed by the reference)
#define N_LIG   100000
#define N_TGT   20000
#define N_EDGE  250000
#define LIG_IN  4
#define TGT_IN  1280
#define HID     128
#define ZCOLS   256           // [y_t (W_tl_l) | z_r (W_lt_r)]

#define MTILES  157
#define N_TGT_PAD (MTILES * 128)   // 20096

// ---------------- scratch (device globals; no allocation allowed) ----------
__device__ float g_accL[(size_t)N_LIG * HID];   // 51.2 MB scatter accumulator
__device__ float g_cntL[N_LIG];
__device__ float g_accT[N_TGT * LIG_IN];
__device__ float g_cntT[N_TGT];
__device__ float g_z[(size_t)N_TGT_PAD * ZCOLS];        // fused target projection
__device__ __nv_bfloat16 g_Bh[ZCOLS * TGT_IN];          // [n, k] hi part
__device__ __nv_bfloat16 g_Bl[ZCOLS * TGT_IN];          // [n, k] lo part
__device__ float g_sl[N_LIG];
__device__ float g_st[N_TGT];

// =================== helpers =================================================
static __device__ __forceinline__ uint32_t smem_u32(const void* p) {
    uint32_t a;
    asm("{ .reg .u64 t; cvta.to.shared.u64 t, %1; cvt.u32.u64 %0, t; }"
        : "=r"(a) : "l"(p));
    return a;
}

static __device__ __forceinline__ void ldmx4(uint32_t* r, uint32_t addr) {
    asm volatile("ldmatrix.sync.aligned.m8n8.x4.shared.b16 {%0,%1,%2,%3}, [%4];"
                 : "=r"(r[0]), "=r"(r[1]), "=r"(r[2]), "=r"(r[3]) : "r"(addr));
}

static __device__ __forceinline__ void mma16816(float* d, const uint32_t* a,
                                                uint32_t b0, uint32_t b1) {
    asm volatile(
        "mma.sync.aligned.m16n8k16.row.col.f32.bf16.bf16.f32 "
        "{%0,%1,%2,%3}, {%4,%5,%6,%7}, {%8,%9}, {%0,%1,%2,%3};"
        : "+f"(d[0]), "+f"(d[1]), "+f"(d[2]), "+f"(d[3])
        : "r"(a[0]), "r"(a[1]), "r"(a[2]), "r"(a[3]), "r"(b0), "r"(b1));
}

static __device__ __forceinline__ void cp16(uint32_t saddr, const void* gaddr) {
    asm volatile("cp.async.cg.shared.global [%0], [%1], 16;"
                 :: "r"(saddr), "l"(gaddr));
}

// ============ W split kernel: g_Bh/g_Bl[n][k] from W_tl_l / W_lt_r =========
__global__ void conv_w_kernel(const float* __restrict__ W_tl_l,
                              const float* __restrict__ W_lt_r) {
    int idx = blockIdx.x * blockDim.x + threadIdx.x;
    if (idx >= ZCOLS * TGT_IN) return;
    int n = idx / TGT_IN;
    int k = idx % TGT_IN;
    float w = (n < HID) ? W_tl_l[k * HID + n] : W_lt_r[k * HID + (n - HID)];
    __nv_bfloat16 h = __float2bfloat16_rn(w);
    __nv_bfloat16 l = __float2bfloat16_rn(w - __bfloat162float(h));
    g_Bh[idx] = h;
    g_Bl[idx] = l;
}

// ============ HMMA GEMM: z[20096,256] = split(x_target) @ split(W)^T ========
// Block 128x128, BK=32, 256 thr, 8 warps (2 m-rows x 4 n-cols), warp 64x32.
// 3-product split: Ah*Bh + Ah*Bl + Al*Bh, fp32 accumulate.
#define GKCH 40                 // 1280 / 32
#define APITCH 80               // bytes per 32-bf16 row (pad kills bank conflicts)
#define SA_BYTES (128 * APITCH) // 10240
// smem: [Ah | Al | Bstage0(Bh|Bl) | Bstage1(Bh|Bl)]
#define OFF_AH 0
#define OFF_AL 10240
#define OFF_B0 20480
#define OFF_B1 40960
#define GSM_TOT 61440

__global__ void __launch_bounds__(256, 2) gemm_mma_kernel(
    const float* __restrict__ X,
    const __nv_bfloat16* __restrict__ Bh,
    const __nv_bfloat16* __restrict__ Bl) {
    extern __shared__ char smem[];
    const uint32_t sb = smem_u32(smem);
    const int tid = threadIdx.x;
    const int lane = tid & 31;
    const int wid = tid >> 5;
    const int warpRow = wid & 1;      // m: 2 x 64
    const int warpCol = wid >> 1;     // n: 4 x 32

    // ---- global A geometry: 2 threads per row, 16 floats each ----
    const int arow = tid >> 1;
    const int ahalf = tid & 1;
    const long growA = (long)blockIdx.y * 128 + arow;
    const bool aval = growA < N_TGT;
    const float* aptr = X + (size_t)(aval ? growA : 0) * TGT_IN + ahalf * 16;
    const uint32_t a_sts = sb + OFF_AH + (uint32_t)(arow * APITCH + ahalf * 32);

    // ---- global B geometry: 2 threads per row, 16 bf16 each ----
    const int brow = tid >> 1;
    const int bhalf = tid & 1;
    const size_t boffg = (size_t)(blockIdx.x * 128 + brow) * TGT_IN + bhalf * 16;
    const __nv_bfloat16* bhp = Bh + boffg;
    const __nv_bfloat16* blp = Bl + boffg;
    const uint32_t b_sts = (uint32_t)(brow * APITCH + bhalf * 32);

    // ---- ldmatrix lane addressing ----
    const uint32_t a_lm = sb + OFF_AH +
        (uint32_t)((warpRow * 64 + (lane & 15)) * APITCH + (lane >> 4) * 16);
    const uint32_t b_lm =
        (uint32_t)((warpCol * 32 + ((lane >> 4) & 1) * 8 + (lane & 7)) * APITCH
                   + ((lane >> 3) & 1) * 16);

    float acc[4][4][4];
    #pragma unroll
    for (int i = 0; i < 4; i++)
        #pragma unroll
        for (int j = 0; j < 4; j++)
            #pragma unroll
            for (int q = 0; q < 4; q++) acc[i][j][q] = 0.f;

    float4 apre[4];

    // ---------- prologue: B chunk0 via cp.async, A chunk0 via LDG ----------
    {
        uint32_t s0 = sb + OFF_B0;
        #pragma unroll
        for (int j = 0; j < 2; j++) {
            cp16(s0 + b_sts + j * 16, bhp + j * 8);
            cp16(s0 + 10240 + b_sts + j * 16, blp + j * 8);
        }
        asm volatile("cp.async.commit_group;");
        if (aval) {
            #pragma unroll
            for (int i = 0; i < 4; i++)
                apre[i] = *(const float4*)(aptr + i * 4);
        } else {
            #pragma unroll
            for (int i = 0; i < 4; i++) apre[i] = make_float4(0.f, 0.f, 0.f, 0.f);
        }
        // convert + STS A chunk 0
        float f[16] = {apre[0].x, apre[0].y, apre[0].z, apre[0].w,
                       apre[1].x, apre[1].y, apre[1].z, apre[1].w,
                       apre[2].x, apre[2].y, apre[2].z, apre[2].w,
                       apre[3].x, apre[3].y, apre[3].z, apre[3].w};
        uint32_t hi[8], lo[8];
        #pragma unroll
        for (int j = 0; j < 8; j++) {
            __nv_bfloat16 h0 = __float2bfloat16_rn(f[2 * j]);
            __nv_bfloat16 h1 = __float2bfloat16_rn(f[2 * j + 1]);
            __nv_bfloat16 l0 = __float2bfloat16_rn(f[2 * j] - __bfloat162float(h0));
            __nv_bfloat16 l1 = __float2bfloat16_rn(f[2 * j + 1] - __bfloat162float(h1));
            __nv_bfloat162 hp = __halves2bfloat162(h0, h1);
            __nv_bfloat162 lp = __halves2bfloat162(l0, l1);
            hi[j] = *reinterpret_cast<uint32_t*>(&hp);
            lo[j] = *reinterpret_cast<uint32_t*>(&lp);
        }
        *(uint4*)(smem + (a_sts - sb)) = make_uint4(hi[0], hi[1], hi[2], hi[3]);
        *(uint4*)(smem + (a_sts - sb) + 16) = make_uint4(hi[4], hi[5], hi[6], hi[7]);
        *(uint4*)(smem + (a_sts - sb) + OFF_AL) = make_uint4(lo[0], lo[1], lo[2], lo[3]);
        *(uint4*)(smem + (a_sts - sb) + OFF_AL + 16) = make_uint4(lo[4], lo[5], lo[6], lo[7]);
        asm volatile("cp.async.wait_group 0;");
        __syncthreads();
    }

    // ---------- main loop ----------
    for (int c = 0; c < GKCH; c++) {
        const bool more = (c + 1) < GKCH;
        if (more) {
            // cp.async B chunk c+1 into the other stage
            uint32_t snext = sb + (((c + 1) & 1) ? OFF_B1 : OFF_B0);
            const __nv_bfloat16* bh2 = bhp + (c + 1) * 32;
            const __nv_bfloat16* bl2 = blp + (c + 1) * 32;
            #pragma unroll
            for (int j = 0; j < 2; j++) {
                cp16(snext + b_sts + j * 16, bh2 + j * 8);
                cp16(snext + 10240 + b_sts + j * 16, bl2 + j * 8);
            }
            asm volatile("cp.async.commit_group;");
            // LDG A chunk c+1 into regs
            if (aval) {
                #pragma unroll
                for (int i = 0; i < 4; i++)
                    apre[i] = *(const float4*)(aptr + (c + 1) * 32 + i * 4);
            }
        }

        // ---- compute on stage c ----
        {
            const uint32_t bstage = sb + ((c & 1) ? OFF_B1 : OFF_B0);
            #pragma unroll
            for (int ks = 0; ks < 2; ks++) {
                uint32_t bhf[2][4], blf[2][4];
                #pragma unroll
                for (int ntp = 0; ntp < 2; ntp++) {
                    ldmx4(bhf[ntp], bstage + b_lm + ntp * (16 * APITCH) + ks * 32);
                    ldmx4(blf[ntp], bstage + 10240 + b_lm + ntp * (16 * APITCH) + ks * 32);
                }
                #pragma unroll
                for (int mt = 0; mt < 4; mt++) {
                    uint32_t ah[4], al[4];
                    ldmx4(ah, a_lm + mt * (16 * APITCH) + ks * 32);
                    ldmx4(al, a_lm + OFF_AL + mt * (16 * APITCH) + ks * 32);
                    #pragma unroll
                    for (int nt = 0; nt < 4; nt++) {
                        uint32_t b0h = bhf[nt >> 1][(nt & 1) * 2];
                        uint32_t b1h = bhf[nt >> 1][(nt & 1) * 2 + 1];
                        mma16816(acc[mt][nt], ah, b0h, b1h);
                        mma16816(acc[mt][nt], ah,
                                 blf[nt >> 1][(nt & 1) * 2],
                                 blf[nt >> 1][(nt & 1) * 2 + 1]);
                        mma16816(acc[mt][nt], al, b0h, b1h);
                    }
                }
            }
        }
        __syncthreads();

        if (more) {
            // convert + STS A chunk c+1 (single A buffer, now safe)
            float f[16] = {apre[0].x, apre[0].y, apre[0].z, apre[0].w,
                           apre[1].x, apre[1].y, apre[1].z, apre[1].w,
                           apre[2].x, apre[2].y, apre[2].z, apre[2].w,
                           apre[3].x, apre[3].y, apre[3].z, apre[3].w};
            uint32_t hi[8], lo[8];
            #pragma unroll
            for (int j = 0; j < 8; j++) {
                float f0 = aval ? f[2 * j] : 0.f;
                float f1 = aval ? f[2 * j + 1] : 0.f;
                __nv_bfloat16 h0 = __float2bfloat16_rn(f0);
                __nv_bfloat16 h1 = __float2bfloat16_rn(f1);
                __nv_bfloat16 l0 = __float2bfloat16_rn(f0 - __bfloat162float(h0));
                __nv_bfloat16 l1 = __float2bfloat16_rn(f1 - __bfloat162float(h1));
                __nv_bfloat162 hp = __halves2bfloat162(h0, h1);
                __nv_bfloat162 lp = __halves2bfloat162(l0, l1);
                hi[j] = *reinterpret_cast<uint32_t*>(&hp);
                lo[j] = *reinterpret_cast<uint32_t*>(&lp);
            }
            uint32_t off = a_sts - sb;
            *(uint4*)(smem + off) = make_uint4(hi[0], hi[1], hi[2], hi[3]);
            *(uint4*)(smem + off + 16) = make_uint4(hi[4], hi[5], hi[6], hi[7]);
            *(uint4*)(smem + off + OFF_AL) = make_uint4(lo[0], lo[1], lo[2], lo[3]);
            *(uint4*)(smem + off + OFF_AL + 16) = make_uint4(lo[4], lo[5], lo[6], lo[7]);
            asm volatile("cp.async.wait_group 0;");
        }
        __syncthreads();
    }

    // ---------- epilogue: write fp32 accumulators to g_z ----------
    const int rbase = blockIdx.y * 128 + warpRow * 64;
    const int cbase = blockIdx.x * 128 + warpCol * 32;
    #pragma unroll
    for (int mt = 0; mt < 4; mt++) {
        #pragma unroll
        for (int nt = 0; nt < 4; nt++) {
            int r0 = rbase + mt * 16 + (lane >> 2);
            int cc = cbase + nt * 8 + (lane & 3) * 2;
            *(float2*)(g_z + (size_t)r0 * ZCOLS + cc) =
                make_float2(acc[mt][nt][0], acc[mt][nt][1]);
            *(float2*)(g_z + (size_t)(r0 + 8) * ZCOLS + cc) =
                make_float2(acc[mt][nt][2], acc[mt][nt][3]);
        }
    }
}

// ---------------- edge scatter: one warp per edge ---------------------------
__global__ __launch_bounds__(256) void edge_scatter_kernel(
    const int* __restrict__ esrc, const int* __restrict__ edst,
    const float* __restrict__ xlig) {
    int warpId = (blockIdx.x * blockDim.x + threadIdx.x) >> 5;
    int lane = threadIdx.x & 31;
    if (warpId >= N_EDGE) return;
    int s = esrc[warpId];
    int d = edst[warpId];
    float4 y = *(const float4*)(g_z + (size_t)d * ZCOLS + lane * 4);
    float4* a = (float4*)(g_accL + (size_t)s * HID + lane * 4);
    atomicAdd(a, y);
    if (lane < 4) {
        atomicAdd(g_accT + (size_t)d * LIG_IN + lane, xlig[(size_t)s * LIG_IN + lane]);
    } else if (lane == 4) {
        atomicAdd(&g_cntL[s], 1.f);
    } else if (lane == 5) {
        atomicAdd(&g_cntT[d], 1.f);
    }
}

// ---------------- target finalize: s_t[t] = <relu(t_out), W_ep[128:256]> ---
__global__ __launch_bounds__(256) void target_final_kernel(
    const float* __restrict__ W_lt_l, const float* __restrict__ b_lt_l,
    const float* __restrict__ W_ep) {
    int t = blockIdx.x * (blockDim.x >> 5) + (threadIdx.x >> 5);
    int lane = threadIdx.x & 31;
    if (t >= N_TGT) return;
    float inv = 1.f / fmaxf(g_cntT[t], 1.f);
    float m0 = g_accT[t * 4 + 0] * inv;
    float m1 = g_accT[t * 4 + 1] * inv;
    float m2 = g_accT[t * 4 + 2] * inv;
    float m3 = g_accT[t * 4 + 3] * inv;
    float sum = 0.f;
    #pragma unroll
    for (int i = 0; i < 4; i++) {
        int h = lane + 32 * i;
        float v = b_lt_l[h] + g_z[(size_t)t * ZCOLS + HID + h];
        v = fmaf(m0, W_lt_l[0 * HID + h], v);
        v = fmaf(m1, W_lt_l[1 * HID + h], v);
        v = fmaf(m2, W_lt_l[2 * HID + h], v);
        v = fmaf(m3, W_lt_l[3 * HID + h], v);
        v = fmaxf(v, 0.f);
        sum = fmaf(v, W_ep[HID + h], sum);
    }
    #pragma unroll
    for (int o = 16; o > 0; o >>= 1) sum += __shfl_xor_sync(0xffffffffu, sum, o);
    if (lane == 0) g_st[t] = sum;
}

// ---------------- ligand finalize: s_l[l] = <relu(l_out), W_ep[0:128]> -----
__global__ __launch_bounds__(256) void ligand_final_kernel(
    const float* __restrict__ xlig, const float* __restrict__ W_tl_r,
    const float* __restrict__ b_tl_l, const float* __restrict__ W_ep) {
    int l = blockIdx.x * (blockDim.x >> 5) + (threadIdx.x >> 5);
    int lane = threadIdx.x & 31;
    if (l >= N_LIG) return;
    float inv = 1.f / fmaxf(g_cntL[l], 1.f);
    float4 xf = *(const float4*)(xlig + (size_t)l * LIG_IN);
    float sum = 0.f;
    #pragma unroll
    for (int i = 0; i < 4; i++) {
        int h = lane + 32 * i;
        float v = b_tl_l[h] + g_accL[(size_t)l * HID + h] * inv;
        v = fmaf(xf.x, W_tl_r[0 * HID + h], v);
        v = fmaf(xf.y, W_tl_r[1 * HID + h], v);
        v = fmaf(xf.z, W_tl_r[2 * HID + h], v);
        v = fmaf(xf.w, W_tl_r[3 * HID + h], v);
        v = fmaxf(v, 0.f);
        sum = fmaf(v, W_ep[h], sum);
    }
    #pragma unroll
    for (int o = 16; o > 0; o >>= 1) sum += __shfl_xor_sync(0xffffffffu, sum, o);
    if (lane == 0) g_sl[l] = sum;
}

// ---------------- edge output ------------------------------------------------
__global__ __launch_bounds__(256) void edge_out_kernel(
    const int* __restrict__ esrc, const int* __restrict__ edst,
    const float* __restrict__ b_ep, float* __restrict__ out) {
    int e = blockIdx.x * blockDim.x + threadIdx.x;
    if (e >= N_EDGE) return;
    out[e] = g_sl[esrc[e]] + g_st[edst[e]] + b_ep[0];
}

// ---------------- launch ----------------------------------------------------
extern "C" void kernel_launch(void* const* d_in, const int* in_sizes, int n_in,
                              void* d_out, int out_size) {
    const float* x_ligand = (const float*)d_in[0];
    const float* x_target = (const float*)d_in[1];
    const int*   edge_src = (const int*)d_in[2];
    const int*   edge_dst = (const int*)d_in[3];
    const float* W_lt_l   = (const float*)d_in[4];
    const float* b_lt_l   = (const float*)d_in[5];
    const float* W_lt_r   = (const float*)d_in[6];
    const float* W_tl_l   = (const float*)d_in[7];
    const float* b_tl_l   = (const float*)d_in[8];
    const float* W_tl_r   = (const float*)d_in[9];
    const float* W_ep     = (const float*)d_in[10];
    const float* b_ep     = (const float*)d_in[11];
    float* out = (float*)d_out;

    // zero the scatter accumulators (graph-capturable async memsets)
    void *pAccL, *pCntL, *pAccT, *pCntT;
    cudaGetSymbolAddress(&pAccL, g_accL);
    cudaGetSymbolAddress(&pCntL, g_cntL);
    cudaGetSymbolAddress(&pAccT, g_accT);
    cudaGetSymbolAddress(&pCntT, g_cntT);
    cudaMemsetAsync(pAccL, 0, (size_t)N_LIG * HID * sizeof(float), 0);
    cudaMemsetAsync(pCntL, 0, (size_t)N_LIG * sizeof(float), 0);
    cudaMemsetAsync(pAccT, 0, (size_t)N_TGT * LIG_IN * sizeof(float), 0);
    cudaMemsetAsync(pCntT, 0, (size_t)N_TGT * sizeof(float), 0);

    // split weights into bf16 hi/lo, [n, k] layout
    conv_w_kernel<<<(ZCOLS * TGT_IN + 255) / 256, 256>>>(W_tl_l, W_lt_r);

    // HMMA GEMM: z = x_target @ [W_tl_l | W_lt_r]
    {
        __nv_bfloat16* bh; cudaGetSymbolAddress((void**)&bh, g_Bh);
        __nv_bfloat16* bl; cudaGetSymbolAddress((void**)&bl, g_Bl);
        cudaFuncSetAttribute(gemm_mma_kernel,
                             cudaFuncAttributeMaxDynamicSharedMemorySize, GSM_TOT);
        dim3 grid(2, MTILES);
        gemm_mma_kernel<<<grid, 256, GSM_TOT>>>(x_target, bh, bl);
    }

    // edge scatter (one warp per edge)
    {
        int warpsPerBlock = 256 / 32;
        int blocks = (N_EDGE + warpsPerBlock - 1) / warpsPerBlock;
        edge_scatter_kernel<<<blocks, 256>>>(edge_src, edge_dst, x_ligand);
    }

    // per-node scalar reductions
    target_final_kernel<<<(N_TGT + 7) / 8, 256>>>(W_lt_l, b_lt_l, W_ep);
    ligand_final_kernel<<<(N_LIG + 7) / 8, 256>>>(x_ligand, W_tl_r, b_tl_l, W_ep);

    // edge predictions
    edge_out_kernel<<<(N_EDGE + 255) / 256, 256>>>(edge_src, edge_dst, b_ep, out);
}

// round 5
// speedup vs baseline: 2.3862x; 1.0127x over previous
#include <cuda_runtime.h>
#include <cuda_bf16.h>
#include <cstdint>

// Problem constants (fixed by the reference)
#define N_LIG   100000
#define N_TGT   20000
#define N_EDGE  250000
#define LIG_IN  4
#define TGT_IN  1280
#define HID     128
#define ZCOLS   256           // [y_t (W_tl_l) | z_r (W_lt_r)]

#define MTILES  157
#define N_TGT_PAD (MTILES * 128)   // 20096

#define SCAN_B 256
#define NBLK ((N_LIG + SCAN_B - 1) / SCAN_B)   // 391

// ---------------- scratch (device globals; no allocation allowed) ----------
__device__ float g_accT[N_TGT * LIG_IN];
__device__ int   g_cntLi[N_LIG];
__device__ int   g_cntTi[N_TGT];
__device__ int   g_offL[N_LIG];
__device__ int   g_woff[N_LIG];
__device__ int   g_part[NBLK];
__device__ int   g_elist[N_EDGE];
__device__ float g_z[(size_t)N_TGT_PAD * ZCOLS];        // fused target projection
__device__ __nv_bfloat16 g_Bh[ZCOLS * TGT_IN];          // [n, k] hi part
__device__ __nv_bfloat16 g_Bl[ZCOLS * TGT_IN];          // [n, k] lo part
__device__ float g_sl[N_LIG];
__device__ float g_st[N_TGT];

// =================== helpers =================================================
static __device__ __forceinline__ uint32_t smem_u32(const void* p) {
    uint32_t a;
    asm("{ .reg .u64 t; cvta.to.shared.u64 t, %1; cvt.u32.u64 %0, t; }"
        : "=r"(a) : "l"(p));
    return a;
}

static __device__ __forceinline__ void ldmx4(uint32_t* r, uint32_t addr) {
    asm volatile("ldmatrix.sync.aligned.m8n8.x4.shared.b16 {%0,%1,%2,%3}, [%4];"
                 : "=r"(r[0]), "=r"(r[1]), "=r"(r[2]), "=r"(r[3]) : "r"(addr));
}

static __device__ __forceinline__ void mma16816(float* d, const uint32_t* a,
                                                uint32_t b0, uint32_t b1) {
    asm volatile(
        "mma.sync.aligned.m16n8k16.row.col.f32.bf16.bf16.f32 "
        "{%0,%1,%2,%3}, {%4,%5,%6,%7}, {%8,%9}, {%0,%1,%2,%3};"
        : "+f"(d[0]), "+f"(d[1]), "+f"(d[2]), "+f"(d[3])
        : "r"(a[0]), "r"(a[1]), "r"(a[2]), "r"(a[3]), "r"(b0), "r"(b1));
}

static __device__ __forceinline__ void cp16(uint32_t saddr, const void* gaddr) {
    asm volatile("cp.async.cg.shared.global [%0], [%1], 16;"
                 :: "r"(saddr), "l"(gaddr));
}

// ============ W split kernel: g_Bh/g_Bl[n][k] from W_tl_l / W_lt_r =========
__global__ void conv_w_kernel(const float* __restrict__ W_tl_l,
                              const float* __restrict__ W_lt_r) {
    int idx = blockIdx.x * blockDim.x + threadIdx.x;
    if (idx >= ZCOLS * TGT_IN) return;
    int n = idx / TGT_IN;
    int k = idx % TGT_IN;
    float w = (n < HID) ? W_tl_l[k * HID + n] : W_lt_r[k * HID + (n - HID)];
    __nv_bfloat16 h = __float2bfloat16_rn(w);
    __nv_bfloat16 l = __float2bfloat16_rn(w - __bfloat162float(h));
    g_Bh[idx] = h;
    g_Bl[idx] = l;
}

// ============ edge light pass: degree histograms + target accumulators ======
__global__ __launch_bounds__(256) void edge_light_kernel(
    const int* __restrict__ esrc, const int* __restrict__ edst,
    const float* __restrict__ xlig) {
    int e = blockIdx.x * blockDim.x + threadIdx.x;
    if (e >= N_EDGE) return;
    int s = esrc[e];
    int d = edst[e];
    atomicAdd(&g_cntLi[s], 1);
    atomicAdd(&g_cntTi[d], 1);
    float4 xf = *(const float4*)(xlig + (size_t)s * LIG_IN);
    float* t = g_accT + (size_t)d * LIG_IN;
    atomicAdd(t + 0, xf.x); atomicAdd(t + 1, xf.y);
    atomicAdd(t + 2, xf.z); atomicAdd(t + 3, xf.w);
}

// ============ exclusive scan over g_cntLi -> g_offL (3 kernels) =============
__global__ __launch_bounds__(SCAN_B) void scan1_kernel() {
    __shared__ int sm[SCAN_B];
    int i = blockIdx.x * SCAN_B + threadIdx.x;
    int v = (i < N_LIG) ? g_cntLi[i] : 0;
    sm[threadIdx.x] = v;
    __syncthreads();
    int incl = v;
    #pragma unroll
    for (int o = 1; o < SCAN_B; o <<= 1) {
        int u = (threadIdx.x >= o) ? sm[threadIdx.x - o] : 0;
        __syncthreads();
        incl += u;
        sm[threadIdx.x] = incl;
        __syncthreads();
    }
    if (i < N_LIG) g_offL[i] = incl - v;
    if (threadIdx.x == SCAN_B - 1) g_part[blockIdx.x] = incl;
}

__global__ __launch_bounds__(512) void scan2_kernel() {
    __shared__ int sm[512];
    int t = threadIdx.x;
    int v = (t < NBLK) ? g_part[t] : 0;
    sm[t] = v;
    __syncthreads();
    int incl = v;
    #pragma unroll
    for (int o = 1; o < 512; o <<= 1) {
        int u = (t >= o) ? sm[t - o] : 0;
        __syncthreads();
        incl += u;
        sm[t] = incl;
        __syncthreads();
    }
    if (t < NBLK) g_part[t] = incl - v;   // exclusive
}

__global__ __launch_bounds__(SCAN_B) void scan3_kernel() {
    int i = blockIdx.x * SCAN_B + threadIdx.x;
    if (i >= N_LIG) return;
    int off = g_offL[i] + g_part[blockIdx.x];
    g_offL[i] = off;
    g_woff[i] = off;
}

// ============ fill edge lists ==============================================
__global__ __launch_bounds__(256) void fill_kernel(
    const int* __restrict__ esrc, const int* __restrict__ edst) {
    int e = blockIdx.x * blockDim.x + threadIdx.x;
    if (e >= N_EDGE) return;
    int pos = atomicAdd(&g_woff[esrc[e]], 1);
    g_elist[pos] = edst[e];
}

// ============ HMMA GEMM: z[20096,256] = split(x_target) @ split(W)^T ========
// Block 128x128, BK=32, 256 thr, 8 warps (2 m-rows x 4 n-cols), warp 64x32.
// 3-product split: Ah*Bh + Ah*Bl + Al*Bh, fp32 accumulate.
// Double-buffered A AND B -> one __syncthreads per K-chunk.
#define GKCH 40                 // 1280 / 32
#define APITCH 80               // bytes per 32-bf16 row (pad kills bank conflicts)
// smem: [Abuf0(Ah|Al) | Abuf1(Ah|Al) | Bstage0(Bh|Bl) | Bstage1(Bh|Bl)]
#define ABUF_STRIDE 20480
#define OFF_B 40960
#define BSTG_STRIDE 20480
#define GSM_TOT 81920

__global__ void __launch_bounds__(256, 2) gemm_mma_kernel(
    const float* __restrict__ X,
    const __nv_bfloat16* __restrict__ Bh,
    const __nv_bfloat16* __restrict__ Bl) {
    extern __shared__ char smem[];
    const uint32_t sb = smem_u32(smem);
    const int tid = threadIdx.x;
    const int lane = tid & 31;
    const int wid = tid >> 5;
    const int warpRow = wid & 1;      // m: 2 x 64
    const int warpCol = wid >> 1;     // n: 4 x 32

    // ---- global A geometry: 2 threads per row, 16 floats each ----
    const int arow = tid >> 1;
    const int ahalf = tid & 1;
    const long growA = (long)blockIdx.y * 128 + arow;
    const bool aval = growA < N_TGT;
    const float* aptr = X + (size_t)(aval ? growA : 0) * TGT_IN + ahalf * 16;
    const uint32_t a_off = (uint32_t)(arow * APITCH + ahalf * 32);

    // ---- global B geometry: 2 threads per row, 16 bf16 each ----
    const int brow = tid >> 1;
    const int bhalf = tid & 1;
    const size_t boffg = (size_t)(blockIdx.x * 128 + brow) * TGT_IN + bhalf * 16;
    const __nv_bfloat16* bhp = Bh + boffg;
    const __nv_bfloat16* blp = Bl + boffg;
    const uint32_t b_sts = (uint32_t)(brow * APITCH + bhalf * 32);

    // ---- ldmatrix lane addressing (relative) ----
    const uint32_t a_lm =
        (uint32_t)((warpRow * 64 + (lane & 15)) * APITCH + (lane >> 4) * 16);
    const uint32_t b_lm =
        (uint32_t)((warpCol * 32 + ((lane >> 4) & 1) * 8 + (lane & 7)) * APITCH
                   + ((lane >> 3) & 1) * 16);

    float acc[4][4][4];
    #pragma unroll
    for (int i = 0; i < 4; i++)
        #pragma unroll
        for (int j = 0; j < 4; j++)
            #pragma unroll
            for (int q = 0; q < 4; q++) acc[i][j][q] = 0.f;

    float4 apre[4];

    // convert + STS helper (lambda-free macro style)
    auto storeA = [&](int buf) {
        float f[16] = {apre[0].x, apre[0].y, apre[0].z, apre[0].w,
                       apre[1].x, apre[1].y, apre[1].z, apre[1].w,
                       apre[2].x, apre[2].y, apre[2].z, apre[2].w,
                       apre[3].x, apre[3].y, apre[3].z, apre[3].w};
        uint32_t hi[8], lo[8];
        #pragma unroll
        for (int j = 0; j < 8; j++) {
            __nv_bfloat16 h0 = __float2bfloat16_rn(f[2 * j]);
            __nv_bfloat16 h1 = __float2bfloat16_rn(f[2 * j + 1]);
            __nv_bfloat16 l0 = __float2bfloat16_rn(f[2 * j] - __bfloat162float(h0));
            __nv_bfloat16 l1 = __float2bfloat16_rn(f[2 * j + 1] - __bfloat162float(h1));
            __nv_bfloat162 hp = __halves2bfloat162(h0, h1);
            __nv_bfloat162 lp = __halves2bfloat162(l0, l1);
            hi[j] = *reinterpret_cast<uint32_t*>(&hp);
            lo[j] = *reinterpret_cast<uint32_t*>(&lp);
        }
        char* base = smem + buf * ABUF_STRIDE + a_off;
        *(uint4*)(base) = make_uint4(hi[0], hi[1], hi[2], hi[3]);
        *(uint4*)(base + 16) = make_uint4(hi[4], hi[5], hi[6], hi[7]);
        *(uint4*)(base + 10240) = make_uint4(lo[0], lo[1], lo[2], lo[3]);
        *(uint4*)(base + 10240 + 16) = make_uint4(lo[4], lo[5], lo[6], lo[7]);
    };

    // ---------- prologue: chunk 0 ----------
    {
        uint32_t s0 = sb + OFF_B;
        #pragma unroll
        for (int j = 0; j < 2; j++) {
            cp16(s0 + b_sts + j * 16, bhp + j * 8);
            cp16(s0 + 10240 + b_sts + j * 16, blp + j * 8);
        }
        asm volatile("cp.async.commit_group;");
        if (aval) {
            #pragma unroll
            for (int i = 0; i < 4; i++)
                apre[i] = *(const float4*)(aptr + i * 4);
        } else {
            #pragma unroll
            for (int i = 0; i < 4; i++) apre[i] = make_float4(0.f, 0.f, 0.f, 0.f);
        }
        storeA(0);
        asm volatile("cp.async.wait_group 0;");
        __syncthreads();
    }

    // ---------- main loop: one sync per chunk ----------
    for (int c = 0; c < GKCH; c++) {
        const bool more = (c + 1) < GKCH;
        if (more) {
            uint32_t snext = sb + OFF_B + ((c + 1) & 1) * BSTG_STRIDE;
            const __nv_bfloat16* bh2 = bhp + (c + 1) * 32;
            const __nv_bfloat16* bl2 = blp + (c + 1) * 32;
            #pragma unroll
            for (int j = 0; j < 2; j++) {
                cp16(snext + b_sts + j * 16, bh2 + j * 8);
                cp16(snext + 10240 + b_sts + j * 16, bl2 + j * 8);
            }
            asm volatile("cp.async.commit_group;");
            if (aval) {
                #pragma unroll
                for (int i = 0; i < 4; i++)
                    apre[i] = *(const float4*)(aptr + (c + 1) * 32 + i * 4);
            }
        }

        // ---- compute on chunk c ----
        {
            const uint32_t abase = sb + (c & 1) * ABUF_STRIDE;
            const uint32_t bstage = sb + OFF_B + (c & 1) * BSTG_STRIDE;
            #pragma unroll
            for (int ks = 0; ks < 2; ks++) {
                uint32_t bhf[2][4], blf[2][4];
                #pragma unroll
                for (int ntp = 0; ntp < 2; ntp++) {
                    ldmx4(bhf[ntp], bstage + b_lm + ntp * (16 * APITCH) + ks * 32);
                    ldmx4(blf[ntp], bstage + 10240 + b_lm + ntp * (16 * APITCH) + ks * 32);
                }
                #pragma unroll
                for (int mt = 0; mt < 4; mt++) {
                    uint32_t ah[4], al[4];
                    ldmx4(ah, abase + a_lm + mt * (16 * APITCH) + ks * 32);
                    ldmx4(al, abase + 10240 + a_lm + mt * (16 * APITCH) + ks * 32);
                    #pragma unroll
                    for (int nt = 0; nt < 4; nt++) {
                        uint32_t b0h = bhf[nt >> 1][(nt & 1) * 2];
                        uint32_t b1h = bhf[nt >> 1][(nt & 1) * 2 + 1];
                        mma16816(acc[mt][nt], ah, b0h, b1h);
                        mma16816(acc[mt][nt], ah,
                                 blf[nt >> 1][(nt & 1) * 2],
                                 blf[nt >> 1][(nt & 1) * 2 + 1]);
                        mma16816(acc[mt][nt], al, b0h, b1h);
                    }
                }
            }
        }

        if (more) {
            storeA((c + 1) & 1);                 // writes the OTHER A buffer
            asm volatile("cp.async.wait_group 0;");
        }
        __syncthreads();
    }

    // ---------- epilogue: write fp32 accumulators to g_z ----------
    const int rbase = blockIdx.y * 128 + warpRow * 64;
    const int cbase = blockIdx.x * 128 + warpCol * 32;
    #pragma unroll
    for (int mt = 0; mt < 4; mt++) {
        #pragma unroll
        for (int nt = 0; nt < 4; nt++) {
            int r0 = rbase + mt * 16 + (lane >> 2);
            int cc = cbase + nt * 8 + (lane & 3) * 2;
            *(float2*)(g_z + (size_t)r0 * ZCOLS + cc) =
                make_float2(acc[mt][nt][0], acc[mt][nt][1]);
            *(float2*)(g_z + (size_t)(r0 + 8) * ZCOLS + cc) =
                make_float2(acc[mt][nt][2], acc[mt][nt][3]);
        }
    }
}

// ---------------- target finalize: s_t[t] = <relu(t_out), W_ep[128:256]> ---
__global__ __launch_bounds__(256) void target_final_kernel(
    const float* __restrict__ W_lt_l, const float* __restrict__ b_lt_l,
    const float* __restrict__ W_ep) {
    int t = blockIdx.x * (blockDim.x >> 5) + (threadIdx.x >> 5);
    int lane = threadIdx.x & 31;
    if (t >= N_TGT) return;
    float inv = 1.f / fmaxf((float)g_cntTi[t], 1.f);
    float m0 = g_accT[t * 4 + 0] * inv;
    float m1 = g_accT[t * 4 + 1] * inv;
    float m2 = g_accT[t * 4 + 2] * inv;
    float m3 = g_accT[t * 4 + 3] * inv;
    float sum = 0.f;
    #pragma unroll
    for (int i = 0; i < 4; i++) {
        int h = lane + 32 * i;
        float v = b_lt_l[h] + g_z[(size_t)t * ZCOLS + HID + h];
        v = fmaf(m0, W_lt_l[0 * HID + h], v);
        v = fmaf(m1, W_lt_l[1 * HID + h], v);
        v = fmaf(m2, W_lt_l[2 * HID + h], v);
        v = fmaf(m3, W_lt_l[3 * HID + h], v);
        v = fmaxf(v, 0.f);
        sum = fmaf(v, W_ep[HID + h], sum);
    }
    #pragma unroll
    for (int o = 16; o > 0; o >>= 1) sum += __shfl_xor_sync(0xffffffffu, sum, o);
    if (lane == 0) g_st[t] = sum;
}

// ---------------- ligand gather + finalize (warp per ligand) ----------------
// acc = sum over edges of y_t[dst]; then mean, bias, self-term, relu, W_ep dot.
__global__ __launch_bounds__(256) void ligand_gather_kernel(
    const float* __restrict__ xlig, const float* __restrict__ W_tl_r,
    const float* __restrict__ b_tl_l, const float* __restrict__ W_ep) {
    int l = blockIdx.x * (blockDim.x >> 5) + (threadIdx.x >> 5);
    int lane = threadIdx.x & 31;
    if (l >= N_LIG) return;
    int start = g_offL[l];
    int cnt = g_cntLi[l];
    float4 acc = make_float4(0.f, 0.f, 0.f, 0.f);
    for (int i = 0; i < cnt; i++) {
        int d = g_elist[start + i];
        float4 y = *((const float4*)(g_z + (size_t)d * ZCOLS) + lane);
        acc.x += y.x; acc.y += y.y; acc.z += y.z; acc.w += y.w;
    }
    float inv = 1.f / fmaxf((float)cnt, 1.f);
    float4 xf = *(const float4*)(xlig + (size_t)l * LIG_IN);
    float m[4] = {acc.x * inv, acc.y * inv, acc.z * inv, acc.w * inv};
    float sum = 0.f;
    #pragma unroll
    for (int j = 0; j < 4; j++) {
        int h = lane * 4 + j;
        float v = b_tl_l[h] + m[j];
        v = fmaf(xf.x, W_tl_r[0 * HID + h], v);
        v = fmaf(xf.y, W_tl_r[1 * HID + h], v);
        v = fmaf(xf.z, W_tl_r[2 * HID + h], v);
        v = fmaf(xf.w, W_tl_r[3 * HID + h], v);
        v = fmaxf(v, 0.f);
        sum = fmaf(v, W_ep[h], sum);
    }
    #pragma unroll
    for (int o = 16; o > 0; o >>= 1) sum += __shfl_xor_sync(0xffffffffu, sum, o);
    if (lane == 0) g_sl[l] = sum;
}

// ---------------- edge output ------------------------------------------------
__global__ __launch_bounds__(256) void edge_out_kernel(
    const int* __restrict__ esrc, const int* __restrict__ edst,
    const float* __restrict__ b_ep, float* __restrict__ out) {
    int e = blockIdx.x * blockDim.x + threadIdx.x;
    if (e >= N_EDGE) return;
    out[e] = g_sl[esrc[e]] + g_st[edst[e]] + b_ep[0];
}

// ---------------- launch ----------------------------------------------------
extern "C" void kernel_launch(void* const* d_in, const int* in_sizes, int n_in,
                              void* d_out, int out_size) {
    const float* x_ligand = (const float*)d_in[0];
    const float* x_target = (const float*)d_in[1];
    const int*   edge_src = (const int*)d_in[2];
    const int*   edge_dst = (const int*)d_in[3];
    const float* W_lt_l   = (const float*)d_in[4];
    const float* b_lt_l   = (const float*)d_in[5];
    const float* W_lt_r   = (const float*)d_in[6];
    const float* W_tl_l   = (const float*)d_in[7];
    const float* b_tl_l   = (const float*)d_in[8];
    const float* W_tl_r   = (const float*)d_in[9];
    const float* W_ep     = (const float*)d_in[10];
    const float* b_ep     = (const float*)d_in[11];
    float* out = (float*)d_out;

    // zero the small accumulators (graph-capturable async memsets)
    void *pAccT, *pCntLi, *pCntTi;
    cudaGetSymbolAddress(&pAccT, g_accT);
    cudaGetSymbolAddress(&pCntLi, g_cntLi);
    cudaGetSymbolAddress(&pCntTi, g_cntTi);
    cudaMemsetAsync(pAccT, 0, (size_t)N_TGT * LIG_IN * sizeof(float), 0);
    cudaMemsetAsync(pCntLi, 0, (size_t)N_LIG * sizeof(int), 0);
    cudaMemsetAsync(pCntTi, 0, (size_t)N_TGT * sizeof(int), 0);

    // split weights into bf16 hi/lo, [n, k] layout
    conv_w_kernel<<<(ZCOLS * TGT_IN + 255) / 256, 256>>>(W_tl_l, W_lt_r);

    // degree histograms + target-side accumulation
    edge_light_kernel<<<(N_EDGE + 255) / 256, 256>>>(edge_src, edge_dst, x_ligand);

    // exclusive scan -> CSR offsets
    scan1_kernel<<<NBLK, SCAN_B>>>();
    scan2_kernel<<<1, 512>>>();
    scan3_kernel<<<NBLK, SCAN_B>>>();

    // fill per-ligand edge lists
    fill_kernel<<<(N_EDGE + 255) / 256, 256>>>(edge_src, edge_dst);

    // HMMA GEMM: z = x_target @ [W_tl_l | W_lt_r]
    {
        __nv_bfloat16* bh; cudaGetSymbolAddress((void**)&bh, g_Bh);
        __nv_bfloat16* bl; cudaGetSymbolAddress((void**)&bl, g_Bl);
        cudaFuncSetAttribute(gemm_mma_kernel,
                             cudaFuncAttributeMaxDynamicSharedMemorySize, GSM_TOT);
        dim3 grid(2, MTILES);
        gemm_mma_kernel<<<grid, 256, GSM_TOT>>>(x_target, bh, bl);
    }

    // per-node scalar reductions
    target_final_kernel<<<(N_TGT + 7) / 8, 256>>>(W_lt_l, b_lt_l, W_ep);
    ligand_gather_kernel<<<(N_LIG + 7) / 8, 256>>>(x_ligand, W_tl_r, b_tl_l, W_ep);

    // edge predictions
    edge_out_kernel<<<(N_EDGE + 255) / 256, 256>>>(edge_src, edge_dst, b_ep, out);
}

// round 6
// speedup vs baseline: 2.5969x; 1.0883x over previous
#include <cuda_runtime.h>
#include <cuda_bf16.h>
#include <cstdint>

// Problem constants (fixed by the reference)
#define N_LIG   100000
#define N_TGT   20000
#define N_EDGE  250000
#define LIG_IN  4
#define TGT_IN  1280
#define HID     128
#define ZCOLS   256           // [y_t (W_tl_l) | z_r (W_lt_r)]

#define MTILES  157
#define N_TGT_PAD (MTILES * 128)   // 20096

#define SCAN_B 256
#define NBLK ((N_LIG + SCAN_B - 1) / SCAN_B)   // 391

// ---------------- scratch (device globals; no allocation allowed) ----------
__device__ float g_accT[N_TGT * LIG_IN];
__device__ int   g_cntLi[N_LIG];
__device__ int   g_cntTi[N_TGT];
__device__ int   g_offL[N_LIG];
__device__ int   g_woff[N_LIG];
__device__ int   g_part[NBLK];
__device__ int   g_elist[N_EDGE];
__device__ float g_z[(size_t)N_TGT_PAD * ZCOLS];        // fused target projection
__device__ __nv_bfloat16 g_Bh[ZCOLS * TGT_IN];          // [n, k] hi part
__device__ __nv_bfloat16 g_Bl[ZCOLS * TGT_IN];          // [n, k] lo part
__device__ float g_sl[N_LIG];
__device__ float g_st[N_TGT];

// =================== helpers =================================================
static __device__ __forceinline__ uint32_t smem_u32(const void* p) {
    uint32_t a;
    asm("{ .reg .u64 t; cvta.to.shared.u64 t, %1; cvt.u32.u64 %0, t; }"
        : "=r"(a) : "l"(p));
    return a;
}

static __device__ __forceinline__ void ldmx4(uint32_t* r, uint32_t addr) {
    asm volatile("ldmatrix.sync.aligned.m8n8.x4.shared.b16 {%0,%1,%2,%3}, [%4];"
                 : "=r"(r[0]), "=r"(r[1]), "=r"(r[2]), "=r"(r[3]) : "r"(addr));
}

static __device__ __forceinline__ void mma16816(float* d, const uint32_t* a,
                                                uint32_t b0, uint32_t b1) {
    asm volatile(
        "mma.sync.aligned.m16n8k16.row.col.f32.bf16.bf16.f32 "
        "{%0,%1,%2,%3}, {%4,%5,%6,%7}, {%8,%9}, {%0,%1,%2,%3};"
        : "+f"(d[0]), "+f"(d[1]), "+f"(d[2]), "+f"(d[3])
        : "r"(a[0]), "r"(a[1]), "r"(a[2]), "r"(a[3]), "r"(b0), "r"(b1));
}

static __device__ __forceinline__ void cp16(uint32_t saddr, const void* gaddr) {
    asm volatile("cp.async.cg.shared.global [%0], [%1], 16;"
                 :: "r"(saddr), "l"(gaddr));
}

// ============ W split kernel: g_Bh/g_Bl[n][k] from W_tl_l / W_lt_r =========
__global__ void conv_w_kernel(const float* __restrict__ W_tl_l,
                              const float* __restrict__ W_lt_r) {
    int idx = blockIdx.x * blockDim.x + threadIdx.x;
    if (idx >= ZCOLS * TGT_IN) return;
    int n = idx / TGT_IN;
    int k = idx % TGT_IN;
    float w = (n < HID) ? W_tl_l[k * HID + n] : W_lt_r[k * HID + (n - HID)];
    __nv_bfloat16 h = __float2bfloat16_rn(w);
    __nv_bfloat16 l = __float2bfloat16_rn(w - __bfloat162float(h));
    g_Bh[idx] = h;
    g_Bl[idx] = l;
}

// ============ edge light pass: degree histograms + target accumulators ======
__global__ __launch_bounds__(256) void edge_light_kernel(
    const int* __restrict__ esrc, const int* __restrict__ edst,
    const float* __restrict__ xlig) {
    int e = blockIdx.x * blockDim.x + threadIdx.x;
    if (e >= N_EDGE) return;
    int s = esrc[e];
    int d = edst[e];
    atomicAdd(&g_cntLi[s], 1);
    atomicAdd(&g_cntTi[d], 1);
    float4 xf = *(const float4*)(xlig + (size_t)s * LIG_IN);
    float* t = g_accT + (size_t)d * LIG_IN;
    atomicAdd(t + 0, xf.x); atomicAdd(t + 1, xf.y);
    atomicAdd(t + 2, xf.z); atomicAdd(t + 3, xf.w);
}

// ============ exclusive scan over g_cntLi -> g_offL (3 kernels) =============
__global__ __launch_bounds__(SCAN_B) void scan1_kernel() {
    __shared__ int sm[SCAN_B];
    int i = blockIdx.x * SCAN_B + threadIdx.x;
    int v = (i < N_LIG) ? g_cntLi[i] : 0;
    sm[threadIdx.x] = v;
    __syncthreads();
    int incl = v;
    #pragma unroll
    for (int o = 1; o < SCAN_B; o <<= 1) {
        int u = (threadIdx.x >= o) ? sm[threadIdx.x - o] : 0;
        __syncthreads();
        incl += u;
        sm[threadIdx.x] = incl;
        __syncthreads();
    }
    if (i < N_LIG) g_offL[i] = incl - v;
    if (threadIdx.x == SCAN_B - 1) g_part[blockIdx.x] = incl;
}

__global__ __launch_bounds__(512) void scan2_kernel() {
    __shared__ int sm[512];
    int t = threadIdx.x;
    int v = (t < NBLK) ? g_part[t] : 0;
    sm[t] = v;
    __syncthreads();
    int incl = v;
    #pragma unroll
    for (int o = 1; o < 512; o <<= 1) {
        int u = (t >= o) ? sm[t - o] : 0;
        __syncthreads();
        incl += u;
        sm[t] = incl;
        __syncthreads();
    }
    if (t < NBLK) g_part[t] = incl - v;   // exclusive
}

__global__ __launch_bounds__(SCAN_B) void scan3_kernel() {
    int i = blockIdx.x * SCAN_B + threadIdx.x;
    if (i >= N_LIG) return;
    int off = g_offL[i] + g_part[blockIdx.x];
    g_offL[i] = off;
    g_woff[i] = off;
}

// ============ fill edge lists ==============================================
__global__ __launch_bounds__(256) void fill_kernel(
    const int* __restrict__ esrc, const int* __restrict__ edst) {
    int e = blockIdx.x * blockDim.x + threadIdx.x;
    if (e >= N_EDGE) return;
    int pos = atomicAdd(&g_woff[esrc[e]], 1);
    g_elist[pos] = edst[e];
}

// ============ HMMA GEMM: z[20096,256] = split(x_target) @ split(W)^T ========
// Block 128x128, BK=32, 256 thr, 8 warps (2 m-rows x 4 n-cols), warp 64x32.
// 3-product split: Ah*Bh + Ah*Bl + Al*Bh, fp32 accumulate.
// Double-buffered A AND B -> one __syncthreads per K-chunk.
#define GKCH 40                 // 1280 / 32
#define APITCH 80               // bytes per 32-bf16 row (pad kills bank conflicts)
// smem: [Abuf0(Ah|Al) | Abuf1(Ah|Al) | Bstage0(Bh|Bl) | Bstage1(Bh|Bl)]
#define ABUF_STRIDE 20480
#define OFF_B 40960
#define BSTG_STRIDE 20480
#define GSM_TOT 81920

__global__ void __launch_bounds__(256, 2) gemm_mma_kernel(
    const float* __restrict__ X,
    const __nv_bfloat16* __restrict__ Bh,
    const __nv_bfloat16* __restrict__ Bl) {
    extern __shared__ char smem[];
    const uint32_t sb = smem_u32(smem);
    const int tid = threadIdx.x;
    const int lane = tid & 31;
    const int wid = tid >> 5;
    const int warpRow = wid & 1;      // m: 2 x 64
    const int warpCol = wid >> 1;     // n: 4 x 32

    // ---- global A geometry: 2 threads per row, 16 floats each ----
    const int arow = tid >> 1;
    const int ahalf = tid & 1;
    const long growA = (long)blockIdx.y * 128 + arow;
    const bool aval = growA < N_TGT;
    const float* aptr = X + (size_t)(aval ? growA : 0) * TGT_IN + ahalf * 16;
    const uint32_t a_off = (uint32_t)(arow * APITCH + ahalf * 32);

    // ---- global B geometry: 2 threads per row, 16 bf16 each ----
    const int brow = tid >> 1;
    const int bhalf = tid & 1;
    const size_t boffg = (size_t)(blockIdx.x * 128 + brow) * TGT_IN + bhalf * 16;
    const __nv_bfloat16* bhp = Bh + boffg;
    const __nv_bfloat16* blp = Bl + boffg;
    const uint32_t b_sts = (uint32_t)(brow * APITCH + bhalf * 32);

    // ---- ldmatrix lane addressing (relative) ----
    const uint32_t a_lm =
        (uint32_t)((warpRow * 64 + (lane & 15)) * APITCH + (lane >> 4) * 16);
    const uint32_t b_lm =
        (uint32_t)((warpCol * 32 + ((lane >> 4) & 1) * 8 + (lane & 7)) * APITCH
                   + ((lane >> 3) & 1) * 16);

    float acc[4][4][4];
    #pragma unroll
    for (int i = 0; i < 4; i++)
        #pragma unroll
        for (int j = 0; j < 4; j++)
            #pragma unroll
            for (int q = 0; q < 4; q++) acc[i][j][q] = 0.f;

    float4 apre[4];

    auto storeA = [&](int buf) {
        float f[16] = {apre[0].x, apre[0].y, apre[0].z, apre[0].w,
                       apre[1].x, apre[1].y, apre[1].z, apre[1].w,
                       apre[2].x, apre[2].y, apre[2].z, apre[2].w,
                       apre[3].x, apre[3].y, apre[3].z, apre[3].w};
        uint32_t hi[8], lo[8];
        #pragma unroll
        for (int j = 0; j < 8; j++) {
            __nv_bfloat16 h0 = __float2bfloat16_rn(f[2 * j]);
            __nv_bfloat16 h1 = __float2bfloat16_rn(f[2 * j + 1]);
            __nv_bfloat16 l0 = __float2bfloat16_rn(f[2 * j] - __bfloat162float(h0));
            __nv_bfloat16 l1 = __float2bfloat16_rn(f[2 * j + 1] - __bfloat162float(h1));
            __nv_bfloat162 hp = __halves2bfloat162(h0, h1);
            __nv_bfloat162 lp = __halves2bfloat162(l0, l1);
            hi[j] = *reinterpret_cast<uint32_t*>(&hp);
            lo[j] = *reinterpret_cast<uint32_t*>(&lp);
        }
        char* base = smem + buf * ABUF_STRIDE + a_off;
        *(uint4*)(base) = make_uint4(hi[0], hi[1], hi[2], hi[3]);
        *(uint4*)(base + 16) = make_uint4(hi[4], hi[5], hi[6], hi[7]);
        *(uint4*)(base + 10240) = make_uint4(lo[0], lo[1], lo[2], lo[3]);
        *(uint4*)(base + 10240 + 16) = make_uint4(lo[4], lo[5], lo[6], lo[7]);
    };

    // ---------- prologue: chunk 0 ----------
    {
        uint32_t s0 = sb + OFF_B;
        #pragma unroll
        for (int j = 0; j < 2; j++) {
            cp16(s0 + b_sts + j * 16, bhp + j * 8);
            cp16(s0 + 10240 + b_sts + j * 16, blp + j * 8);
        }
        asm volatile("cp.async.commit_group;");
        if (aval) {
            #pragma unroll
            for (int i = 0; i < 4; i++)
                apre[i] = *(const float4*)(aptr + i * 4);
        } else {
            #pragma unroll
            for (int i = 0; i < 4; i++) apre[i] = make_float4(0.f, 0.f, 0.f, 0.f);
        }
        storeA(0);
        asm volatile("cp.async.wait_group 0;");
        __syncthreads();
    }

    // ---------- main loop: one sync per chunk ----------
    for (int c = 0; c < GKCH; c++) {
        const bool more = (c + 1) < GKCH;
        if (more) {
            uint32_t snext = sb + OFF_B + ((c + 1) & 1) * BSTG_STRIDE;
            const __nv_bfloat16* bh2 = bhp + (c + 1) * 32;
            const __nv_bfloat16* bl2 = blp + (c + 1) * 32;
            #pragma unroll
            for (int j = 0; j < 2; j++) {
                cp16(snext + b_sts + j * 16, bh2 + j * 8);
                cp16(snext + 10240 + b_sts + j * 16, bl2 + j * 8);
            }
            asm volatile("cp.async.commit_group;");
            if (aval) {
                #pragma unroll
                for (int i = 0; i < 4; i++)
                    apre[i] = *(const float4*)(aptr + (c + 1) * 32 + i * 4);
            }
        }

        // ---- compute on chunk c ----
        {
            const uint32_t abase = sb + (c & 1) * ABUF_STRIDE;
            const uint32_t bstage = sb + OFF_B + (c & 1) * BSTG_STRIDE;
            #pragma unroll
            for (int ks = 0; ks < 2; ks++) {
                uint32_t bhf[2][4], blf[2][4];
                #pragma unroll
                for (int ntp = 0; ntp < 2; ntp++) {
                    ldmx4(bhf[ntp], bstage + b_lm + ntp * (16 * APITCH) + ks * 32);
                    ldmx4(blf[ntp], bstage + 10240 + b_lm + ntp * (16 * APITCH) + ks * 32);
                }
                #pragma unroll
                for (int mt = 0; mt < 4; mt++) {
                    uint32_t ah[4], al[4];
                    ldmx4(ah, abase + a_lm + mt * (16 * APITCH) + ks * 32);
                    ldmx4(al, abase + 10240 + a_lm + mt * (16 * APITCH) + ks * 32);
                    #pragma unroll
                    for (int nt = 0; nt < 4; nt++) {
                        uint32_t b0h = bhf[nt >> 1][(nt & 1) * 2];
                        uint32_t b1h = bhf[nt >> 1][(nt & 1) * 2 + 1];
                        mma16816(acc[mt][nt], ah, b0h, b1h);
                        mma16816(acc[mt][nt], ah,
                                 blf[nt >> 1][(nt & 1) * 2],
                                 blf[nt >> 1][(nt & 1) * 2 + 1]);
                        mma16816(acc[mt][nt], al, b0h, b1h);
                    }
                }
            }
        }

        if (more) {
            storeA((c + 1) & 1);                 // writes the OTHER A buffer
            asm volatile("cp.async.wait_group 0;");
        }
        __syncthreads();
    }

    // ---------- epilogue: write fp32 accumulators to g_z ----------
    const int rbase = blockIdx.y * 128 + warpRow * 64;
    const int cbase = blockIdx.x * 128 + warpCol * 32;
    #pragma unroll
    for (int mt = 0; mt < 4; mt++) {
        #pragma unroll
        for (int nt = 0; nt < 4; nt++) {
            int r0 = rbase + mt * 16 + (lane >> 2);
            int cc = cbase + nt * 8 + (lane & 3) * 2;
            *(float2*)(g_z + (size_t)r0 * ZCOLS + cc) =
                make_float2(acc[mt][nt][0], acc[mt][nt][1]);
            *(float2*)(g_z + (size_t)(r0 + 8) * ZCOLS + cc) =
                make_float2(acc[mt][nt][2], acc[mt][nt][3]);
        }
    }
}

// ---------------- target finalize: s_t[t] = <relu(t_out), W_ep[128:256]> ---
__global__ __launch_bounds__(256) void target_final_kernel(
    const float* __restrict__ W_lt_l, const float* __restrict__ b_lt_l,
    const float* __restrict__ W_ep) {
    int t = blockIdx.x * (blockDim.x >> 5) + (threadIdx.x >> 5);
    int lane = threadIdx.x & 31;
    if (t >= N_TGT) return;
    float inv = 1.f / fmaxf((float)g_cntTi[t], 1.f);
    float m0 = g_accT[t * 4 + 0] * inv;
    float m1 = g_accT[t * 4 + 1] * inv;
    float m2 = g_accT[t * 4 + 2] * inv;
    float m3 = g_accT[t * 4 + 3] * inv;
    float sum = 0.f;
    #pragma unroll
    for (int i = 0; i < 4; i++) {
        int h = lane + 32 * i;
        float v = b_lt_l[h] + g_z[(size_t)t * ZCOLS + HID + h];
        v = fmaf(m0, W_lt_l[0 * HID + h], v);
        v = fmaf(m1, W_lt_l[1 * HID + h], v);
        v = fmaf(m2, W_lt_l[2 * HID + h], v);
        v = fmaf(m3, W_lt_l[3 * HID + h], v);
        v = fmaxf(v, 0.f);
        sum = fmaf(v, W_ep[HID + h], sum);
    }
    #pragma unroll
    for (int o = 16; o > 0; o >>= 1) sum += __shfl_xor_sync(0xffffffffu, sum, o);
    if (lane == 0) g_st[t] = sum;
}

// ---------------- ligand gather + finalize (warp per ligand) ----------------
__global__ __launch_bounds__(256) void ligand_gather_kernel(
    const float* __restrict__ xlig, const float* __restrict__ W_tl_r,
    const float* __restrict__ b_tl_l, const float* __restrict__ W_ep) {
    int l = blockIdx.x * (blockDim.x >> 5) + (threadIdx.x >> 5);
    int lane = threadIdx.x & 31;
    if (l >= N_LIG) return;
    int start = g_offL[l];
    int cnt = g_cntLi[l];
    float4 acc = make_float4(0.f, 0.f, 0.f, 0.f);
    for (int i = 0; i < cnt; i++) {
        int d = g_elist[start + i];
        float4 y = *((const float4*)(g_z + (size_t)d * ZCOLS) + lane);
        acc.x += y.x; acc.y += y.y; acc.z += y.z; acc.w += y.w;
    }
    float inv = 1.f / fmaxf((float)cnt, 1.f);
    float4 xf = *(const float4*)(xlig + (size_t)l * LIG_IN);
    float m[4] = {acc.x * inv, acc.y * inv, acc.z * inv, acc.w * inv};
    float sum = 0.f;
    #pragma unroll
    for (int j = 0; j < 4; j++) {
        int h = lane * 4 + j;
        float v = b_tl_l[h] + m[j];
        v = fmaf(xf.x, W_tl_r[0 * HID + h], v);
        v = fmaf(xf.y, W_tl_r[1 * HID + h], v);
        v = fmaf(xf.z, W_tl_r[2 * HID + h], v);
        v = fmaf(xf.w, W_tl_r[3 * HID + h], v);
        v = fmaxf(v, 0.f);
        sum = fmaf(v, W_ep[h], sum);
    }
    #pragma unroll
    for (int o = 16; o > 0; o >>= 1) sum += __shfl_xor_sync(0xffffffffu, sum, o);
    if (lane == 0) g_sl[l] = sum;
}

// ---------------- edge output ------------------------------------------------
__global__ __launch_bounds__(256) void edge_out_kernel(
    const int* __restrict__ esrc, const int* __restrict__ edst,
    const float* __restrict__ b_ep, float* __restrict__ out) {
    int e = blockIdx.x * blockDim.x + threadIdx.x;
    if (e >= N_EDGE) return;
    out[e] = g_sl[esrc[e]] + g_st[edst[e]] + b_ep[0];
}

// ---------------- launch: fork/join across two streams ----------------------
extern "C" void kernel_launch(void* const* d_in, const int* in_sizes, int n_in,
                              void* d_out, int out_size) {
    const float* x_ligand = (const float*)d_in[0];
    const float* x_target = (const float*)d_in[1];
    const int*   edge_src = (const int*)d_in[2];
    const int*   edge_dst = (const int*)d_in[3];
    const float* W_lt_l   = (const float*)d_in[4];
    const float* b_lt_l   = (const float*)d_in[5];
    const float* W_lt_r   = (const float*)d_in[6];
    const float* W_tl_l   = (const float*)d_in[7];
    const float* b_tl_l   = (const float*)d_in[8];
    const float* W_tl_r   = (const float*)d_in[9];
    const float* W_ep     = (const float*)d_in[10];
    const float* b_ep     = (const float*)d_in[11];
    float* out = (float*)d_out;

    // one-time host resources (streams/events are not device memory)
    static cudaStream_t s1 = nullptr;
    static cudaEvent_t evRoot = nullptr, evG = nullptr, ev1 = nullptr, ev2 = nullptr;
    if (!s1) {
        cudaStreamCreateWithFlags(&s1, cudaStreamNonBlocking);
        cudaEventCreateWithFlags(&evRoot, cudaEventDisableTiming);
        cudaEventCreateWithFlags(&evG, cudaEventDisableTiming);
        cudaEventCreateWithFlags(&ev1, cudaEventDisableTiming);
        cudaEventCreateWithFlags(&ev2, cudaEventDisableTiming);
    }
    cudaStream_t s0 = 0;   // capturing (legacy) stream

    // ---- fork s1 off the captured stream ----
    cudaEventRecord(evRoot, s0);
    cudaStreamWaitEvent(s1, evRoot, 0);

    // ================= side stream s1: edge/CSR pipeline =================
    {
        void *pAccT, *pCntLi, *pCntTi;
        cudaGetSymbolAddress(&pAccT, g_accT);
        cudaGetSymbolAddress(&pCntLi, g_cntLi);
        cudaGetSymbolAddress(&pCntTi, g_cntTi);
        cudaMemsetAsync(pAccT, 0, (size_t)N_TGT * LIG_IN * sizeof(float), s1);
        cudaMemsetAsync(pCntLi, 0, (size_t)N_LIG * sizeof(int), s1);
        cudaMemsetAsync(pCntTi, 0, (size_t)N_TGT * sizeof(int), s1);

        edge_light_kernel<<<(N_EDGE + 255) / 256, 256, 0, s1>>>(edge_src, edge_dst, x_ligand);
        scan1_kernel<<<NBLK, SCAN_B, 0, s1>>>();
        scan2_kernel<<<1, 512, 0, s1>>>();
        scan3_kernel<<<NBLK, SCAN_B, 0, s1>>>();
        fill_kernel<<<(N_EDGE + 255) / 256, 256, 0, s1>>>(edge_src, edge_dst);
        cudaEventRecord(ev1, s1);   // CSR + accT ready
    }

    // ================= main stream s0: weights + GEMM ====================
    conv_w_kernel<<<(ZCOLS * TGT_IN + 255) / 256, 256, 0, s0>>>(W_tl_l, W_lt_r);
    {
        __nv_bfloat16* bh; cudaGetSymbolAddress((void**)&bh, g_Bh);
        __nv_bfloat16* bl; cudaGetSymbolAddress((void**)&bl, g_Bl);
        cudaFuncSetAttribute(gemm_mma_kernel,
                             cudaFuncAttributeMaxDynamicSharedMemorySize, GSM_TOT);
        dim3 grid(2, MTILES);
        gemm_mma_kernel<<<grid, 256, GSM_TOT, s0>>>(x_target, bh, bl);
    }
    cudaEventRecord(evG, s0);       // g_z ready

    // s1: target_final needs g_z (evG) and its own accT (program order)
    cudaStreamWaitEvent(s1, evG, 0);
    target_final_kernel<<<(N_TGT + 7) / 8, 256, 0, s1>>>(W_lt_l, b_lt_l, W_ep);
    cudaEventRecord(ev2, s1);

    // s0: ligand_gather needs g_z (program order) + CSR (ev1)
    cudaStreamWaitEvent(s0, ev1, 0);
    ligand_gather_kernel<<<(N_LIG + 7) / 8, 256, 0, s0>>>(x_ligand, W_tl_r, b_tl_l, W_ep);

    // join: edge_out needs s_l (program order) + s_t (ev2)
    cudaStreamWaitEvent(s0, ev2, 0);
    edge_out_kernel<<<(N_EDGE + 255) / 256, 256, 0, s0>>>(edge_src, edge_dst, b_ep, out);
}